// round 3
// baseline (speedup 1.0000x reference)
#include <cuda_runtime.h>

// AdaptiveSudokuLoss: ce + 0.5 * constraint + 0.1 * entropy, fused single kernel.
// outputs: (B, 81, 9) fp32, targets: (B, 81) int32, out: scalar fp32.
//
// 256 threads/block; each iteration processes a trio of 3 batch elements
// (243 active lanes, one cell each). Softmax in registers, probs staged in
// smem (address = tid*9+j, conflict-free), 27 constraint sums per batch
// element in phase 2. Grid-stride over trios. Last block (threadfence+ticket)
// does the deterministic final reduction and writes the scalar.

#define THREADS 256
#define GRID 1776   // 12 * 148 SMs

__device__ float g_ce[GRID];
__device__ float g_cons[GRID];
__device__ float g_conf[GRID];
__device__ unsigned int g_count = 0;

__global__ __launch_bounds__(THREADS)
void sudoku_loss_fused(const float* __restrict__ outp,
                       const int* __restrict__ tgt,
                       int Bn,
                       float* __restrict__ d_out)
{
    __shared__ float sp[3 * 729];       // probs for 3 batch elements
    const int tid = threadIdx.x;
    const int ntrio = (Bn + 2) / 3;

    float ce_acc = 0.f, cons_acc = 0.f, conf_acc = 0.f;

    for (int ti = blockIdx.x; ti < ntrio; ti += gridDim.x) {
        const int b0 = ti * 3;

        // -------- phase 1: per-cell softmax, ce, entropy; probs -> smem ------
        if (tid < 243) {
            const int bl = tid / 81;         // 0..2
            const int b  = b0 + bl;
            if (b < Bn) {
                const int cell = tid - bl * 81;
                const float* x = outp + ((size_t)b * 81 + cell) * 9;
                float v[9];
                #pragma unroll
                for (int j = 0; j < 9; j++) v[j] = x[j];

                float m = v[0];
                #pragma unroll
                for (int j = 1; j < 9; j++) m = fmaxf(m, v[j]);

                float e[9];
                float s = 0.f;
                #pragma unroll
                for (int j = 0; j < 9; j++) { e[j] = __expf(v[j] - m); s += e[j]; }

                const float inv = __frcp_rn(s);
                float sx = 0.f;
                #pragma unroll
                for (int j = 0; j < 9; j++) {
                    const float p = e[j] * inv;
                    sp[tid * 9 + j] = p;        // == bl*729 + cell*9 + j
                    sx = fmaf(p, v[j], sx);
                }
                const float lse = m + __logf(s);

                const int t = tgt[(size_t)b * 81 + cell];
                float xt = 0.f;
                #pragma unroll
                for (int j = 0; j < 9; j++) xt += (j == t) ? v[j] : 0.f;

                ce_acc   += lse - xt;   // -logp[target]
                conf_acc += lse - sx;   // entropy
            }
        }
        __syncthreads();

        // -------- phase 2: 27 constraint sums per batch element -------------
        if (tid < 243) {
            const int bl = tid / 81;
            if (b0 + bl < Bn) {
                const int rem = tid - bl * 81;
                const int idx = rem / 9;
                const int d   = rem - idx * 9;
                const float* p = sp + bl * 729;

                float rs = 0.f, cs = 0.f, bs = 0.f;
                #pragma unroll
                for (int c = 0; c < 9; c++) rs += p[(idx * 9 + c) * 9 + d];
                #pragma unroll
                for (int r = 0; r < 9; r++) cs += p[(r * 9 + idx) * 9 + d];
                const int br = idx / 3, bc = idx - br * 3;
                #pragma unroll
                for (int dr = 0; dr < 3; dr++)
                    #pragma unroll
                    for (int dc = 0; dc < 3; dc++)
                        bs += p[((br * 3 + dr) * 9 + (bc * 3 + dc)) * 9 + d];

                rs -= 1.f; cs -= 1.f; bs -= 1.f;
                cons_acc += rs * rs + cs * cs + bs * bs;
            }
        }
        __syncthreads();
    }

    // -------- block reduction: 3 scalars over 8 warps ------------------------
    #pragma unroll
    for (int o = 16; o > 0; o >>= 1) {
        ce_acc   += __shfl_down_sync(0xffffffffu, ce_acc,   o);
        cons_acc += __shfl_down_sync(0xffffffffu, cons_acc, o);
        conf_acc += __shfl_down_sync(0xffffffffu, conf_acc, o);
    }
    __shared__ float wr[8][3];
    const int wid = tid >> 5, lid = tid & 31;
    if (lid == 0) { wr[wid][0] = ce_acc; wr[wid][1] = cons_acc; wr[wid][2] = conf_acc; }
    __syncthreads();

    __shared__ bool is_last;
    if (tid == 0) {
        float a = 0.f, b = 0.f, c = 0.f;
        #pragma unroll
        for (int w = 0; w < 8; w++) { a += wr[w][0]; b += wr[w][1]; c += wr[w][2]; }
        g_ce[blockIdx.x]   = a;
        g_cons[blockIdx.x] = b;
        g_conf[blockIdx.x] = c;
        __threadfence();
        const unsigned ticket = atomicAdd(&g_count, 1u);
        is_last = (ticket == gridDim.x - 1);
        if (is_last) g_count = 0;           // reset for graph replay
    }
    __syncthreads();

    // -------- last block: deterministic final reduce + combine ---------------
    if (is_last) {
        float a = 0.f, b = 0.f, c = 0.f;
        for (int i = tid; i < (int)gridDim.x; i += THREADS) {
            a += g_ce[i]; b += g_cons[i]; c += g_conf[i];
        }
        #pragma unroll
        for (int o = 16; o > 0; o >>= 1) {
            a += __shfl_down_sync(0xffffffffu, a, o);
            b += __shfl_down_sync(0xffffffffu, b, o);
            c += __shfl_down_sync(0xffffffffu, c, o);
        }
        if (lid == 0) { wr[wid][0] = a; wr[wid][1] = b; wr[wid][2] = c; }
        __syncthreads();
        if (tid == 0) {
            float fa = 0.f, fb = 0.f, fc = 0.f;
            #pragma unroll
            for (int w = 0; w < 8; w++) { fa += wr[w][0]; fb += wr[w][1]; fc += wr[w][2]; }
            const float Ncells = (float)Bn * 81.0f;
            d_out[0] = fa / Ncells
                     + 0.5f * fb / ((float)Bn * 9.0f * 27.0f)
                     + 0.1f * fc / (Ncells + 1e-8f);
        }
    }
}

extern "C" void kernel_launch(void* const* d_in, const int* in_sizes, int n_in,
                              void* d_out, int out_size)
{
    const float* outp = (const float*)d_in[0];   // (B, 81, 9) fp32
    const int*   tgt  = (const int*)d_in[1];     // (B, 81) int32
    float*       out  = (float*)d_out;

    const int Bn = in_sizes[0] / (81 * 9);
    sudoku_loss_fused<<<GRID, THREADS>>>(outp, tgt, Bn, out);
}